// round 13
// baseline (speedup 1.0000x reference)
#include <cuda_runtime.h>
#include <cuda_bf16.h>
#include <cuda_fp16.h>

#define BB   64
#define DD   128
#define NPER 512
#define NTOT (BB*NPER)
#define AB   (1.0f/512.0f)

__device__ __forceinline__ unsigned saddr(const void* p){unsigned a;
    asm("{.reg .u64 t; cvta.to.shared.u64 t, %1; cvt.u32.u64 %0, t;}":"=r"(a):"l"(p)); return a;}
__device__ __forceinline__ void st_peer(unsigned a, unsigned rk, float v){
    unsigned pa; asm("mapa.shared::cluster.u32 %0, %1, %2;":"=r"(pa):"r"(a),"r"(rk));
    asm volatile("st.shared::cluster.f32 [%0], %1;"::"r"(pa),"f"(v));}
#define CL_SYNC() do{ asm volatile("barrier.cluster.arrive.aligned;":::"memory"); \
                      asm volatile("barrier.cluster.wait.aligned;":::"memory"); }while(0)

// packed 2^x for P0 = exp(10*d) = 2^(d*10*log2e), straight to half2 bits
__device__ __forceinline__ unsigned exp10h2(float d0, float d1){
    unsigned h;
    float x0 = d0*14.426950408889634f, x1 = d1*14.426950408889634f;
    asm("cvt.rn.f16x2.f32 %0, %1, %2;" : "=r"(h) : "f"(x1), "f"(x0));
    asm("ex2.approx.f16x2 %0, %0;" : "+r"(h));
    return h;
}

// Multi-row butterfly: rs[0..7] per-lane partials for 8 rows; full cross-lane
// sum; lane l ends holding row ((l>>2)&7).
__device__ __forceinline__ float mrow8(float* rs, int l)
{
    bool h4 = l & 16;
    #pragma unroll
    for (int j=0;j<4;j++){
        float send = h4 ? rs[j] : rs[j+4];
        float recv = __shfl_xor_sync(0xffffffffu, send, 16);
        rs[j] = (h4 ? rs[j+4] : rs[j]) + recv;
    }
    bool h3 = l & 8;
    #pragma unroll
    for (int j=0;j<2;j++){
        float send = h3 ? rs[j] : rs[j+2];
        float recv = __shfl_xor_sync(0xffffffffu, send, 8);
        rs[j] = (h3 ? rs[j+2] : rs[j]) + recv;
    }
    bool h2 = l & 4;
    {
        float send = h2 ? rs[0] : rs[1];
        float recv = __shfl_xor_sync(0xffffffffu, send, 4);
        rs[0] = (h2 ? rs[1] : rs[0]) + recv;
    }
    rs[0] += __shfl_xor_sync(0xffffffffu, rs[0], 2);
    rs[0] += __shfl_xor_sync(0xffffffffu, rs[0], 1);
    return rs[0];
}

// ---- static device scratch ----
__device__ __align__(16) __half        g_P0h[(size_t)BB*NPER*NPER]; // 32 MB
__device__ __align__(16) __nv_bfloat16 g_C  [(size_t)BB*NPER*NPER]; // 32 MB
__device__ __align__(16) __half g_snh[NTOT*DD], g_sth[NTOT*DD];     // fp16 normalized
__device__ float g_sg[BB*DD],  g_qg[BB*DD];
__device__ float g_eb[4*BB];
__device__ float g_gpart[BB];

// ---- fused L2-normalize; nodes/tokens -> fp16, globals -> fp32 ----
__global__ void knorm_all(const float* __restrict__ a, const float* __restrict__ b,
                          const float* __restrict__ c, const float* __restrict__ d)
{
    int gid = blockIdx.x * 8 + threadIdx.y;
    const float* in; int row, sel;
    if      (gid < NTOT)        { in=a; row=gid;           sel=0; }
    else if (gid < 2*NTOT)      { in=b; row=gid-NTOT;      sel=1; }
    else if (gid < 2*NTOT+BB)   { in=c; row=gid-2*NTOT;    sel=2; }
    else if (gid < 2*NTOT+2*BB) { in=d; row=gid-2*NTOT-BB; sel=3; }
    else return;
    int l = threadIdx.x;
    float4 x = ((const float4*)(in + (size_t)row*DD))[l];
    float ss = x.x*x.x + x.y*x.y + x.z*x.z + x.w*x.w;
    #pragma unroll
    for (int o=16;o;o>>=1) ss += __shfl_xor_sync(0xffffffffu, ss, o);
    float inv = 1.0f / fmaxf(sqrtf(ss), 1e-12f);
    x.x*=inv; x.y*=inv; x.z*=inv; x.w*=inv;
    if (sel < 2) {
        __half* out = (sel==0) ? g_snh : g_sth;
        __half2 h0 = __floats2half2_rn(x.x, x.y);
        __half2 h1 = __floats2half2_rn(x.z, x.w);
        uint2 pk; pk.x = *(unsigned*)&h0; pk.y = *(unsigned*)&h1;
        *(uint2*)(out + (size_t)row*DD + l*4) = pk;
    } else {
        float* out = (sel==2) ? g_sg : g_qg;
        ((float4*)(out + (size_t)row*DD))[l] = x;
    }
}

// ---- global NT-Xent ----
__global__ void __launch_bounds__(128) kglobal()
{
    __shared__ float si[DD], qi[DD], simbuf[128], lse[2];
    int i = blockIdx.x, t = threadIdx.x;
    si[t] = g_sg[i*DD + t];
    qi[t] = g_qg[i*DD + t];
    __syncthreads();
    int j = t & 63, half = t >> 6;
    const float* other = (half==0) ? (g_qg + (size_t)j*DD) : (g_sg + (size_t)j*DD);
    const float* mine  = (half==0) ? si : qi;
    float d = 0.f;
    #pragma unroll 8
    for (int k=0;k<DD;k++) d = fmaf(mine[k], other[k], d);
    simbuf[t] = d * 10.f;
    __syncthreads();
    if (t==0 || t==64) {
        float m = -1e30f;
        for (int k=0;k<64;k++) m = fmaxf(m, simbuf[half*64+k]);
        float s = 0.f;
        for (int k=0;k<64;k++) s += expf(simbuf[half*64+k] - m);
        lse[half] = m + logf(s);
    }
    __syncthreads();
    if (t==0) {
        float sii = simbuf[i];
        g_gpart[i] = -(2.f*sii - lse[0] - lse[1]) * (1.0f/(2.0f*BB));
    }
}

// ---- tensor-core build: D = A·B^T via mma.sync m16n8k16; exp via ex2.f16x2 ----
__global__ void __launch_bounds__(256) kbuild_mma()
{
    int b = blockIdx.z, i0 = blockIdx.y*128, j0 = blockIdx.x*128;
    int w = threadIdx.x >> 5, l = threadIdx.x & 31;
    int r0 = i0 + w*16 + (l >> 2);
    int kc = (l & 3) * 2;

    const __half* A = g_snh + ((size_t)b*NPER + r0)*DD;
    unsigned a[8][4];
    #pragma unroll
    for (int k8=0;k8<8;k8++) {
        int k0 = k8*16;
        a[k8][0] = *(const unsigned*)(A + k0 + kc);
        a[k8][1] = *(const unsigned*)(A + 8*DD + k0 + kc);
        a[k8][2] = *(const unsigned*)(A + k0 + kc + 8);
        a[k8][3] = *(const unsigned*)(A + 8*DD + k0 + kc + 8);
    }

    const __half* Bp = g_sth + ((size_t)b*NPER + j0 + (l >> 2))*DD;
    for (int n0=0; n0<128; n0+=8) {
        float d0=0.f, d1=0.f, d2=0.f, d3=0.f;
        const __half* Bn = Bp + (size_t)n0*DD;
        #pragma unroll
        for (int k8=0;k8<8;k8++) {
            unsigned b0 = *(const unsigned*)(Bn + k8*16 + kc);
            unsigned b1 = *(const unsigned*)(Bn + k8*16 + kc + 8);
            asm("mma.sync.aligned.m16n8k16.row.col.f32.f16.f16.f32 "
                "{%0,%1,%2,%3},{%4,%5,%6,%7},{%8,%9},{%0,%1,%2,%3};"
                : "+f"(d0),"+f"(d1),"+f"(d2),"+f"(d3)
                : "r"(a[k8][0]),"r"(a[k8][1]),"r"(a[k8][2]),"r"(a[k8][3]),
                  "r"(b0),"r"(b1));
        }
        size_t off0 = ((size_t)b*NPER + r0)*NPER + j0 + n0 + kc;
        size_t off1 = off0 + (size_t)8*NPER;
        *(unsigned*)(g_P0h+off0) = exp10h2(d0, d1);
        *(unsigned*)(g_P0h+off1) = exp10h2(d2, d3);
        __nv_bfloat162 c0, c1;
        c0.x=__float2bfloat16_rn(-d0); c0.y=__float2bfloat16_rn(-d1);
        c1.x=__float2bfloat16_rn(-d2); c1.y=__float2bfloat16_rn(-d3);
        *(__nv_bfloat162*)(g_C+off0) = c0;
        *(__nv_bfloat162*)(g_C+off1) = c1;
    }
}

// ---- persistent Sinkhorn: cluster of 4 CTAs / example, 512 thr, 2 CTA/SM ----
// CTA rank r owns rows r*128..+127. 16 warps = 8 rowgroups x 2 colgroups:
// warp (rg,cg): rows rg*16..+15, lane l owns cols cg*256 + l*8..+7.
// Column partials all-pushed to the 4 cluster CTAs (ping-pong slots).
__global__ void __launch_bounds__(512,2) __cluster_dims__(4,1,1) ksinkp4()
{
    __shared__ float  vsm[NPER];
    __shared__ __half vhsm[NPER];
    __shared__ float  usm[2][128];
    __shared__ __half uhsm[2][128];
    __shared__ float  rpart[2][128];
    __shared__ float  cps[8][NPER];        // 16 KB
    __shared__ float  colpart[2][4][NPER]; // 16 KB ping-pong, written by all ranks
    __shared__ float  wsum[16];

    int b = blockIdx.x >> 2, t = threadIdx.x;
    unsigned rank; asm("mov.u32 %0, %%cluster_ctarank;" : "=r"(rank));
    int w = t >> 5, l = t & 31;
    int rg = w >> 1, cg = w & 1;
    int col0 = cg*256 + l*8;

    vsm[t] = AB; vhsm[t] = __float2half_rn(AB);
    if (t < 128) { usm[0][t] = AB; uhsm[0][t] = __float2half_rn(AB); }
    __syncthreads();

    const uint4* Pb = (const uint4*)(g_P0h + ((size_t)(b*NPER + rank*128 + rg*16))*NPER)
                      + cg*32 + l;

    for (int it = 0; it < 100; it++) {
        int pin = it & 1, pout = pin ^ 1;
        uint4 vv = *(const uint4*)&vhsm[col0];
        __half2 vh0 = *(__half2*)&vv.x, vh1 = *(__half2*)&vv.y;
        __half2 vh2 = *(__half2*)&vv.z, vh3 = *(__half2*)&vv.w;
        float accf[8];
        #pragma unroll
        for (int k=0;k<8;k++) accf[k] = 0.f;

        #pragma unroll
        for (int c=0; c<2; c++) {
            float rs[8];
            __half2 hz = __floats2half2_rn(0.f, 0.f);
            __half2 ca0 = hz, ca1 = hz, ca2 = hz, ca3 = hz;
            #pragma unroll
            for (int rr=0; rr<8; rr++) {
                int row = c*8 + rr;
                uint4 pk = Pb[(size_t)row * 64];
                __half2 p0 = *(__half2*)&pk.x, p1 = *(__half2*)&pk.y;
                __half2 p2 = *(__half2*)&pk.z, p3 = *(__half2*)&pk.w;
                __half2 uu = __half2half2(uhsm[pin][rg*16 + row]);
                __half2 s2 = __hmul2(p0, vh0);
                s2 = __hfma2(p1, vh1, s2);
                s2 = __hfma2(p2, vh2, s2);
                s2 = __hfma2(p3, vh3, s2);
                ca0 = __hfma2(p0, uu, ca0);
                ca1 = __hfma2(p1, uu, ca1);
                ca2 = __hfma2(p2, uu, ca2);
                ca3 = __hfma2(p3, uu, ca3);
                rs[rr] = __low2float(s2) + __high2float(s2);
            }
            float rsum = mrow8(rs, l);
            if ((l & 3) == 0)
                rpart[cg][rg*16 + c*8 + ((l>>2)&7)] = rsum;
            float2 f;
            f = __half22float2(ca0); accf[0]+=f.x; accf[1]+=f.y;
            f = __half22float2(ca1); accf[2]+=f.x; accf[3]+=f.y;
            f = __half22float2(ca2); accf[4]+=f.x; accf[5]+=f.y;
            f = __half22float2(ca3); accf[6]+=f.x; accf[7]+=f.y;
        }
        float4* cp = (float4*)&cps[rg][col0];
        cp[0] = make_float4(accf[0], accf[1], accf[2], accf[3]);
        cp[1] = make_float4(accf[4], accf[5], accf[6], accf[7]);
        __syncthreads();

        // all 512 threads: own column partial, push to all 4 cluster CTAs
        {
            float sown = 0.f;
            #pragma unroll
            for (int g=0; g<8; g++) sown += cps[g][t];
            unsigned la = saddr(&colpart[pin][rank][t]);
            #pragma unroll
            for (unsigned r=0; r<4; r++) st_peer(la, r, sown);
        }
        if (t < 128) {                        // u for own 128 rows
            float s = rpart[0][t] + rpart[1][t];
            float un = AB / s;
            if (!isfinite(un)) un = AB;
            usm[pout][t] = un;
            uhsm[pout][t] = __float2half_rn(un);
        }
        CL_SYNC();                            // all pushes visible cluster-wide
        {
            float s = (colpart[pin][0][t] + colpart[pin][1][t])
                    + (colpart[pin][2][t] + colpart[pin][3][t]);
            float vn = AB / s;
            if (!isfinite(vn)) vn = AB;
            vsm[t] = vn;
            vhsm[t] = __float2half_rn(vn);
        }
        __syncthreads();
    }

    // fused epilogue (fp32): sum u_i * P_ij * v_j * C_ij over own 128 rows
    float2 va0 = *(const float2*)&vsm[col0+0];
    float2 va1 = *(const float2*)&vsm[col0+2];
    float2 va2 = *(const float2*)&vsm[col0+4];
    float2 va3 = *(const float2*)&vsm[col0+6];
    const uint4* Cb = (const uint4*)(g_C + ((size_t)(b*NPER + rank*128 + rg*16))*NPER)
                      + cg*32 + l;
    float acc = 0.f;
    #pragma unroll 2
    for (int rr = 0; rr < 16; rr++) {
        uint4 pk = Pb[(size_t)rr * 64];
        uint4 ck = Cb[(size_t)rr * 64];
        float ui = usm[0][rg*16 + rr];
        float2 pf0 = __half22float2(*(__half2*)&pk.x);
        float2 pf1 = __half22float2(*(__half2*)&pk.y);
        float2 pf2 = __half22float2(*(__half2*)&pk.z);
        float2 pf3 = __half22float2(*(__half2*)&pk.w);
        float2 cf0 = __bfloat1622float2(*(__nv_bfloat162*)&ck.x);
        float2 cf1 = __bfloat1622float2(*(__nv_bfloat162*)&ck.y);
        float2 cf2 = __bfloat1622float2(*(__nv_bfloat162*)&ck.z);
        float2 cf3 = __bfloat1622float2(*(__nv_bfloat162*)&ck.w);
        float rsum = (pf0.x*va0.x*cf0.x + pf0.y*va0.y*cf0.y)
                   + (pf1.x*va1.x*cf1.x + pf1.y*va1.y*cf1.y)
                   + (pf2.x*va2.x*cf2.x + pf2.y*va2.y*cf2.y)
                   + (pf3.x*va3.x*cf3.x + pf3.y*va3.y*cf3.y);
        acc = fmaf(ui, rsum, acc);
    }
    #pragma unroll
    for (int o=16;o;o>>=1) acc += __shfl_xor_sync(0xffffffffu, acc, o);
    if (l == 0) wsum[w] = acc;
    __syncthreads();
    if (w == 0) {
        float x = (l < 16) ? wsum[l] : 0.f;
        #pragma unroll
        for (int o=16;o;o>>=1) x += __shfl_xor_sync(0xffffffffu, x, o);
        if (l == 0) g_eb[blockIdx.x] = x;
    }
    CL_SYNC();   // don't exit while peers may still push to our DSMEM
}

// ---- final deterministic reduce ----
__global__ void __launch_bounds__(256) kfinal(float* __restrict__ out)
{
    __shared__ float se[256], sg_[256];
    int t = threadIdx.x;
    se[t]  = g_eb[t];
    sg_[t] = (t < BB) ? g_gpart[t] : 0.f;
    __syncthreads();
    for (int o=128;o;o>>=1) {
        if (t < o) { se[t] += se[t+o]; sg_[t] += sg_[t+o]; }
        __syncthreads();
    }
    if (t == 0) {
        float glob = sg_[0];
        float loc  = se[0] / (float)BB;
        out[0] = glob; out[1] = loc; out[2] = glob + loc;
    }
}

extern "C" void kernel_launch(void* const* d_in, const int* in_sizes, int n_in,
                              void* d_out, int out_size)
{
    const float* struct_global = (const float*)d_in[0];
    const float* seq_global    = (const float*)d_in[1];
    const float* struct_nodes  = (const float*)d_in[2];
    const float* seq_tokens    = (const float*)d_in[3];
    (void)in_sizes; (void)n_in; (void)out_size;

    dim3 tb(32, 8);
    int rows = 2*NTOT + 2*BB;
    knorm_all<<<(rows+7)/8, tb>>>(struct_nodes, seq_tokens, struct_global, seq_global);

    kglobal<<<BB, 128>>>();
    kbuild_mma<<<dim3(4, 4, BB), 256>>>();
    ksinkp4<<<4*BB, 512>>>();
    kfinal<<<1, 256>>>((float*)d_out);
}

// round 17
// speedup vs baseline: 1.0248x; 1.0248x over previous
#include <cuda_runtime.h>
#include <cuda_bf16.h>
#include <cuda_fp16.h>

#define BB   64
#define DD   128
#define NPER 512
#define NTOT (BB*NPER)
#define AB   (1.0f/512.0f)
#define SROW 136   // padded smem row (halfs): 272B, 16B-aligned, bank-shifted

__device__ __forceinline__ unsigned saddr(const void* p){unsigned a;
    asm("{.reg .u64 t; cvta.to.shared.u64 t, %1; cvt.u32.u64 %0, t;}":"=r"(a):"l"(p)); return a;}
__device__ __forceinline__ float ld_peer(unsigned a, unsigned peer){
    unsigned pa; asm("mapa.shared::cluster.u32 %0, %1, %2;":"=r"(pa):"r"(a),"r"(peer));
    float f; asm volatile("ld.shared::cluster.f32 %0, [%1];":"=f"(f):"r"(pa)); return f;}
#define CL_SYNC() do{ asm volatile("barrier.cluster.arrive.aligned;":::"memory"); \
                      asm volatile("barrier.cluster.wait.aligned;":::"memory"); }while(0)

// Multi-row butterfly: rs[0..7] per-lane partials for 8 rows; full cross-lane
// sum; lane l ends holding row ((l>>2)&7).
__device__ __forceinline__ float mrow8(float* rs, int l)
{
    bool h4 = l & 16;
    #pragma unroll
    for (int j=0;j<4;j++){
        float send = h4 ? rs[j] : rs[j+4];
        float recv = __shfl_xor_sync(0xffffffffu, send, 16);
        rs[j] = (h4 ? rs[j+4] : rs[j]) + recv;
    }
    bool h3 = l & 8;
    #pragma unroll
    for (int j=0;j<2;j++){
        float send = h3 ? rs[j] : rs[j+2];
        float recv = __shfl_xor_sync(0xffffffffu, send, 8);
        rs[j] = (h3 ? rs[j+2] : rs[j]) + recv;
    }
    bool h2 = l & 4;
    {
        float send = h2 ? rs[0] : rs[1];
        float recv = __shfl_xor_sync(0xffffffffu, send, 4);
        rs[0] = (h2 ? rs[1] : rs[0]) + recv;
    }
    rs[0] += __shfl_xor_sync(0xffffffffu, rs[0], 2);
    rs[0] += __shfl_xor_sync(0xffffffffu, rs[0], 1);
    return rs[0];
}

// ---- static device scratch ----
__device__ __align__(16) __half        g_P0h[(size_t)BB*NPER*NPER]; // 32 MB
__device__ __align__(16) __nv_bfloat16 g_C  [(size_t)BB*NPER*NPER]; // 32 MB
__device__ __align__(16) __half g_snh[NTOT*DD], g_sth[NTOT*DD];     // fp16 normalized
__device__ float g_sg[BB*DD],  g_qg[BB*DD];
__device__ float g_eb[2*BB];
__device__ float g_gpart[BB];

// ---- fused L2-normalize; nodes/tokens -> fp16, globals -> fp32 ----
__global__ void knorm_all(const float* __restrict__ a, const float* __restrict__ b,
                          const float* __restrict__ c, const float* __restrict__ d)
{
    int gid = blockIdx.x * 8 + threadIdx.y;
    const float* in; int row, sel;
    if      (gid < NTOT)        { in=a; row=gid;           sel=0; }
    else if (gid < 2*NTOT)      { in=b; row=gid-NTOT;      sel=1; }
    else if (gid < 2*NTOT+BB)   { in=c; row=gid-2*NTOT;    sel=2; }
    else if (gid < 2*NTOT+2*BB) { in=d; row=gid-2*NTOT-BB; sel=3; }
    else return;
    int l = threadIdx.x;
    float4 x = ((const float4*)(in + (size_t)row*DD))[l];
    float ss = x.x*x.x + x.y*x.y + x.z*x.z + x.w*x.w;
    #pragma unroll
    for (int o=16;o;o>>=1) ss += __shfl_xor_sync(0xffffffffu, ss, o);
    float inv = 1.0f / fmaxf(sqrtf(ss), 1e-12f);
    x.x*=inv; x.y*=inv; x.z*=inv; x.w*=inv;
    if (sel < 2) {
        __half* out = (sel==0) ? g_snh : g_sth;
        __half2 h0 = __floats2half2_rn(x.x, x.y);
        __half2 h1 = __floats2half2_rn(x.z, x.w);
        uint2 pk; pk.x = *(unsigned*)&h0; pk.y = *(unsigned*)&h1;
        *(uint2*)(out + (size_t)row*DD + l*4) = pk;
    } else {
        float* out = (sel==2) ? g_sg : g_qg;
        ((float4*)(out + (size_t)row*DD))[l] = x;
    }
}

// ---- global NT-Xent ----
__global__ void __launch_bounds__(128) kglobal()
{
    __shared__ float si[DD], qi[DD], simbuf[128], lse[2];
    int i = blockIdx.x, t = threadIdx.x;
    si[t] = g_sg[i*DD + t];
    qi[t] = g_qg[i*DD + t];
    __syncthreads();
    int j = t & 63, half = t >> 6;
    const float* other = (half==0) ? (g_qg + (size_t)j*DD) : (g_sg + (size_t)j*DD);
    const float* mine  = (half==0) ? si : qi;
    float d = 0.f;
    #pragma unroll 8
    for (int k=0;k<DD;k++) d = fmaf(mine[k], other[k], d);
    simbuf[t] = d * 10.f;
    __syncthreads();
    if (t==0 || t==64) {
        float m = -1e30f;
        for (int k=0;k<64;k++) m = fmaxf(m, simbuf[half*64+k]);
        float s = 0.f;
        for (int k=0;k<64;k++) s += expf(simbuf[half*64+k] - m);
        lse[half] = m + logf(s);
    }
    __syncthreads();
    if (t==0) {
        float sii = simbuf[i];
        g_gpart[i] = -(2.f*sii - lse[0] - lse[1]) * (1.0f/(2.0f*BB));
    }
}

// ---- tensor-core build with SMEM-staged coalesced output ----
// CTA = 128x128 tile; mma.sync m16n8k16; fragment results staged in padded
// SMEM, then stored as contiguous per-row uint4s (full coalescing).
__global__ void __launch_bounds__(256) kbuild_mma()
{
    extern __shared__ char sbuf[];
    __half*        sP = (__half*)sbuf;                       // [128][SROW]
    __nv_bfloat16* sC = (__nv_bfloat16*)(sbuf + 128*SROW*2); // [128][SROW]

    int b = blockIdx.z, i0 = blockIdx.y*128, j0 = blockIdx.x*128;
    int w = threadIdx.x >> 5, l = threadIdx.x & 31;
    int rl = w*16 + (l >> 2);               // local tile row (0..127)
    int kc = (l & 3) * 2;

    const __half* A = g_snh + ((size_t)(b*NPER + i0 + rl))*DD;
    unsigned a[8][4];
    #pragma unroll
    for (int k8=0;k8<8;k8++) {
        int k0 = k8*16;
        a[k8][0] = *(const unsigned*)(A + k0 + kc);
        a[k8][1] = *(const unsigned*)(A + 8*DD + k0 + kc);
        a[k8][2] = *(const unsigned*)(A + k0 + kc + 8);
        a[k8][3] = *(const unsigned*)(A + 8*DD + k0 + kc + 8);
    }

    const __half* Bp = g_sth + ((size_t)(b*NPER + j0 + (l >> 2)))*DD;
    for (int n0=0; n0<128; n0+=8) {
        float d0=0.f, d1=0.f, d2=0.f, d3=0.f;
        const __half* Bn = Bp + (size_t)n0*DD;
        #pragma unroll
        for (int k8=0;k8<8;k8++) {
            unsigned b0 = *(const unsigned*)(Bn + k8*16 + kc);
            unsigned b1 = *(const unsigned*)(Bn + k8*16 + kc + 8);
            asm("mma.sync.aligned.m16n8k16.row.col.f32.f16.f16.f32 "
                "{%0,%1,%2,%3},{%4,%5,%6,%7},{%8,%9},{%0,%1,%2,%3};"
                : "+f"(d0),"+f"(d1),"+f"(d2),"+f"(d3)
                : "r"(a[k8][0]),"r"(a[k8][1]),"r"(a[k8][2]),"r"(a[k8][3]),
                  "r"(b0),"r"(b1));
        }
        int cb = n0 + kc;
        *(__half2*)&sP[rl*SROW + cb]     = __floats2half2_rn(__expf(10.f*d0), __expf(10.f*d1));
        *(__half2*)&sP[(rl+8)*SROW + cb] = __floats2half2_rn(__expf(10.f*d2), __expf(10.f*d3));
        __nv_bfloat162 c0, c1;
        c0.x=__float2bfloat16_rn(-d0); c0.y=__float2bfloat16_rn(-d1);
        c1.x=__float2bfloat16_rn(-d2); c1.y=__float2bfloat16_rn(-d3);
        *(__nv_bfloat162*)&sC[rl*SROW + cb]     = c0;
        *(__nv_bfloat162*)&sC[(rl+8)*SROW + cb] = c1;
    }
    __syncthreads();

    // coalesced stores: 128 rows x 16 uint4 per row, per array
    int t = threadIdx.x;
    for (int i = t; i < 128*16; i += 256) {
        int row = i >> 4, q = i & 15;
        size_t goff = ((size_t)(b*NPER + i0 + row))*NPER + j0 + q*8;
        *(uint4*)(g_P0h + goff) = *(uint4*)&sP[row*SROW + q*8];
        *(uint4*)(g_C  + goff)  = *(uint4*)&sC[row*SROW + q*8];
    }
}

// ---- persistent Sinkhorn: cluster of 2 CTAs per example (fp16 streaming) ----
__global__ void __launch_bounds__(1024) __cluster_dims__(2,1,1) ksinkp2()
{
    __shared__ float  vsm[NPER];
    __shared__ __half vhsm[NPER];
    __shared__ float  usm[2][256];
    __shared__ __half uhsm[2][256];
    __shared__ float  rpart[2][256];
    __shared__ float  cps[16][NPER];
    __shared__ float  colpart[2][NPER];   // ping-pong, read by peer
    __shared__ float  wsum[32];

    int b = blockIdx.x >> 1, t = threadIdx.x;
    unsigned rank; asm("mov.u32 %0, %%cluster_ctarank;" : "=r"(rank));
    unsigned peer = rank ^ 1u;
    int w = t >> 5, l = t & 31;
    int rg = w >> 1, cg = w & 1;
    int col0 = cg*256 + l*8;

    if (t < NPER) { vsm[t] = AB; vhsm[t] = __float2half_rn(AB); }
    else if (t < NPER + 256) { usm[0][t-NPER] = AB; uhsm[0][t-NPER] = __float2half_rn(AB); }
    __syncthreads();

    const uint4* Pb = (const uint4*)(g_P0h + ((size_t)(b*NPER + rank*256 + rg*16))*NPER)
                      + cg*32 + l;

    for (int it = 0; it < 100; it++) {
        int pin = it & 1, pout = pin ^ 1;
        uint4 vv = *(const uint4*)&vhsm[col0];
        __half2 vh0 = *(__half2*)&vv.x, vh1 = *(__half2*)&vv.y;
        __half2 vh2 = *(__half2*)&vv.z, vh3 = *(__half2*)&vv.w;
        float accf[8];
        #pragma unroll
        for (int k=0;k<8;k++) accf[k] = 0.f;

        #pragma unroll
        for (int c=0; c<2; c++) {
            float rs[8];
            __half2 hz = __floats2half2_rn(0.f, 0.f);
            __half2 ca0 = hz, ca1 = hz, ca2 = hz, ca3 = hz;
            #pragma unroll
            for (int rr=0; rr<8; rr++) {
                int row = c*8 + rr;
                uint4 pk = Pb[(size_t)row * 64];
                __half2 p0 = *(__half2*)&pk.x, p1 = *(__half2*)&pk.y;
                __half2 p2 = *(__half2*)&pk.z, p3 = *(__half2*)&pk.w;
                __half2 uu = __half2half2(uhsm[pin][rg*16 + row]);
                __half2 s2 = __hmul2(p0, vh0);
                s2 = __hfma2(p1, vh1, s2);
                s2 = __hfma2(p2, vh2, s2);
                s2 = __hfma2(p3, vh3, s2);
                ca0 = __hfma2(p0, uu, ca0);
                ca1 = __hfma2(p1, uu, ca1);
                ca2 = __hfma2(p2, uu, ca2);
                ca3 = __hfma2(p3, uu, ca3);
                rs[rr] = __low2float(s2) + __high2float(s2);
            }
            float rsum = mrow8(rs, l);
            if ((l & 3) == 0)
                rpart[cg][rg*16 + c*8 + ((l>>2)&7)] = rsum;
            float2 f;
            f = __half22float2(ca0); accf[0]+=f.x; accf[1]+=f.y;
            f = __half22float2(ca1); accf[2]+=f.x; accf[3]+=f.y;
            f = __half22float2(ca2); accf[4]+=f.x; accf[5]+=f.y;
            f = __half22float2(ca3); accf[6]+=f.x; accf[7]+=f.y;
        }
        float4* cp = (float4*)&cps[rg][col0];
        cp[0] = make_float4(accf[0], accf[1], accf[2], accf[3]);
        cp[1] = make_float4(accf[4], accf[5], accf[6], accf[7]);
        __syncthreads();

        float sown = 0.f;
        if (t < NPER) {
            #pragma unroll
            for (int g=0; g<16; g++) sown += cps[g][t];
            colpart[pin][t] = sown;
        } else if (t < NPER + 256) {
            int r = t - NPER;
            float s = rpart[0][r] + rpart[1][r];
            float un = AB / s;
            if (!isfinite(un)) un = AB;
            usm[pout][r] = un;
            uhsm[pout][r] = __float2half_rn(un);
        }
        CL_SYNC();
        if (t < NPER) {
            float pv = ld_peer(saddr(&colpart[pin][t]), peer);
            float vn = AB / (sown + pv);
            if (!isfinite(vn)) vn = AB;
            vsm[t] = vn;
            vhsm[t] = __float2half_rn(vn);
        }
        __syncthreads();
    }

    // fused epilogue (fp32): sum u_i * P_ij * v_j * C_ij over own 256 rows
    float2 va0 = *(const float2*)&vsm[col0+0];
    float2 va1 = *(const float2*)&vsm[col0+2];
    float2 va2 = *(const float2*)&vsm[col0+4];
    float2 va3 = *(const float2*)&vsm[col0+6];
    const uint4* Cb = (const uint4*)(g_C + ((size_t)(b*NPER + rank*256 + rg*16))*NPER)
                      + cg*32 + l;
    float acc = 0.f;
    #pragma unroll 2
    for (int rr = 0; rr < 16; rr++) {
        uint4 pk = Pb[(size_t)rr * 64];
        uint4 ck = Cb[(size_t)rr * 64];
        float ui = usm[0][rg*16 + rr];
        float2 pf0 = __half22float2(*(__half2*)&pk.x);
        float2 pf1 = __half22float2(*(__half2*)&pk.y);
        float2 pf2 = __half22float2(*(__half2*)&pk.z);
        float2 pf3 = __half22float2(*(__half2*)&pk.w);
        float2 cf0 = __bfloat1622float2(*(__nv_bfloat162*)&ck.x);
        float2 cf1 = __bfloat1622float2(*(__nv_bfloat162*)&ck.y);
        float2 cf2 = __bfloat1622float2(*(__nv_bfloat162*)&ck.z);
        float2 cf3 = __bfloat1622float2(*(__nv_bfloat162*)&ck.w);
        float rsum = (pf0.x*va0.x*cf0.x + pf0.y*va0.y*cf0.y)
                   + (pf1.x*va1.x*cf1.x + pf1.y*va1.y*cf1.y)
                   + (pf2.x*va2.x*cf2.x + pf2.y*va2.y*cf2.y)
                   + (pf3.x*va3.x*cf3.x + pf3.y*va3.y*cf3.y);
        acc = fmaf(ui, rsum, acc);
    }
    #pragma unroll
    for (int o=16;o;o>>=1) acc += __shfl_xor_sync(0xffffffffu, acc, o);
    if (l == 0) wsum[w] = acc;
    __syncthreads();
    if (w == 0) {
        float x = wsum[l];
        #pragma unroll
        for (int o=16;o;o>>=1) x += __shfl_xor_sync(0xffffffffu, x, o);
        if (l == 0) g_eb[blockIdx.x] = x;
    }
    CL_SYNC();   // don't exit while peer may still read our DSMEM
}

// ---- final deterministic reduce ----
__global__ void __launch_bounds__(128) kfinal(float* __restrict__ out)
{
    __shared__ float se[128], sg_[128];
    int t = threadIdx.x;
    se[t]  = g_eb[t];
    sg_[t] = (t < BB) ? g_gpart[t] : 0.f;
    __syncthreads();
    for (int o=64;o;o>>=1) {
        if (t < o) { se[t] += se[t+o]; sg_[t] += sg_[t+o]; }
        __syncthreads();
    }
    if (t == 0) {
        float glob = sg_[0];
        float loc  = se[0] / (float)BB;
        out[0] = glob; out[1] = loc; out[2] = glob + loc;
    }
}

extern "C" void kernel_launch(void* const* d_in, const int* in_sizes, int n_in,
                              void* d_out, int out_size)
{
    const float* struct_global = (const float*)d_in[0];
    const float* seq_global    = (const float*)d_in[1];
    const float* struct_nodes  = (const float*)d_in[2];
    const float* seq_tokens    = (const float*)d_in[3];
    (void)in_sizes; (void)n_in; (void)out_size;

    int sm_bytes = 2 * 128 * SROW * 2;   // 69,632 B dynamic smem
    cudaFuncSetAttribute(kbuild_mma, cudaFuncAttributeMaxDynamicSharedMemorySize, sm_bytes);

    dim3 tb(32, 8);
    int rows = 2*NTOT + 2*BB;
    knorm_all<<<(rows+7)/8, tb>>>(struct_nodes, seq_tokens, struct_global, seq_global);

    kglobal<<<BB, 128>>>();
    kbuild_mma<<<dim3(4, 4, BB), 256, sm_bytes>>>();
    ksinkp2<<<2*BB, 1024>>>();
    kfinal<<<1, 128>>>((float*)d_out);
}